// round 3
// baseline (speedup 1.0000x reference)
#include <cuda_runtime.h>

#define NPR    16384   // values per row
#define NBINS  100
#define THREADS 256
#define WARPS  (THREADS / 32)
#define HSTRIDE 104    // padded sub-histogram stride (words)

__global__ __launch_bounds__(THREADS)
void hist_rows_kernel(const float* __restrict__ x, float* __restrict__ out)
{
    __shared__ int hist[WARPS * HSTRIDE];

    const int tid = threadIdx.x;

    // Zero sub-histograms
    #pragma unroll
    for (int i = tid; i < WARPS * HSTRIDE; i += THREADS)
        hist[i] = 0;
    __syncthreads();

    int* h = &hist[(tid >> 5) * HSTRIDE];

    const float4* row =
        reinterpret_cast<const float4*>(x) + (size_t)blockIdx.x * (NPR / 4);

    // 16 float4 per thread, unroll 4 to balance MLP vs register pressure
    #pragma unroll 4
    for (int i = 0; i < NPR / (4 * THREADS); i++) {
        float4 v = row[i * THREADS + tid];
        // exact reference semantics: trunc to int, then floor(100*xi/256).
        // 100*xi < 2^16 and /256 is exact -> integer (xi*100)>>8 is bit-exact.
        int b0 = ((int)v.x * NBINS) >> 8;
        int b1 = ((int)v.y * NBINS) >> 8;
        int b2 = ((int)v.z * NBINS) >> 8;
        int b3 = ((int)v.w * NBINS) >> 8;
        atomicAdd(&h[b0], 1);
        atomicAdd(&h[b1], 1);
        atomicAdd(&h[b2], 1);
        atomicAdd(&h[b3], 1);
    }
    __syncthreads();

    // Reduce the 8 per-warp sub-histograms and emit float counts
    for (int b = tid; b < NBINS; b += THREADS) {
        int s = 0;
        #pragma unroll
        for (int w = 0; w < WARPS; w++)
            s += hist[w * HSTRIDE + b];
        out[(size_t)blockIdx.x * NBINS + b] = (float)s;
    }
}

extern "C" void kernel_launch(void* const* d_in, const int* in_sizes, int n_in,
                              void* d_out, int out_size)
{
    const float* x = (const float*)d_in[0];
    float* out = (float*)d_out;
    const int rows = out_size / NBINS;   // 4096
    hist_rows_kernel<<<rows, THREADS>>>(x, out);
}

// round 4
// speedup vs baseline: 1.0149x; 1.0149x over previous
#include <cuda_runtime.h>

#define NPR     16384            // values per row
#define NBINS   100
#define THREADS 256
#define NSUB    (THREADS / 16)   // 16 half-warp sub-histograms
#define HSTRIDE 104              // padded stride (104 % 32 == 8 -> bank shift between regions)
#define F4_PER_THREAD (NPR / (4 * THREADS))  // 16
#define BATCH   8                // float4 staged per batch (MLP)

__global__ __launch_bounds__(THREADS)
void hist_rows_kernel(const float* __restrict__ x, float* __restrict__ out)
{
    __shared__ int hist[NSUB * HSTRIDE];

    const int tid = threadIdx.x;

    // Zero sub-histograms
    #pragma unroll
    for (int i = tid; i < NSUB * HSTRIDE; i += THREADS)
        hist[i] = 0;
    __syncthreads();

    // Half-warp-private region: lanes 0-15 and 16-31 of each warp get
    // separate histograms -> ~2x fewer same-address ATOMS collisions.
    int* h = &hist[(tid >> 4) * HSTRIDE];

    const float4* row =
        reinterpret_cast<const float4*>(x) + (size_t)blockIdx.x * (NPR / 4);

    #pragma unroll
    for (int outer = 0; outer < F4_PER_THREAD / BATCH; outer++) {
        // Stage BATCH loads first: MLP = 8 outstanding LDG.128 per warp
        float4 v[BATCH];
        #pragma unroll
        for (int j = 0; j < BATCH; j++)
            v[j] = __ldcs(&row[(outer * BATCH + j) * THREADS + tid]);

        // Then drain into shared atomics.
        // Exact ref semantics: trunc->int, then floor(100*xi/256) == (xi*100)>>8
        // (exact: 100*xi < 2^16, /256 is a power of two).
        #pragma unroll
        for (int j = 0; j < BATCH; j++) {
            atomicAdd(&h[((int)v[j].x * NBINS) >> 8], 1);
            atomicAdd(&h[((int)v[j].y * NBINS) >> 8], 1);
            atomicAdd(&h[((int)v[j].z * NBINS) >> 8], 1);
            atomicAdd(&h[((int)v[j].w * NBINS) >> 8], 1);
        }
    }
    __syncthreads();

    // Reduce 16 sub-histograms and emit float counts
    for (int b = tid; b < NBINS; b += THREADS) {
        int s = 0;
        #pragma unroll
        for (int w = 0; w < NSUB; w++)
            s += hist[w * HSTRIDE + b];
        out[(size_t)blockIdx.x * NBINS + b] = (float)s;
    }
}

extern "C" void kernel_launch(void* const* d_in, const int* in_sizes, int n_in,
                              void* d_out, int out_size)
{
    const float* x = (const float*)d_in[0];
    float* out = (float*)d_out;
    const int rows = out_size / NBINS;   // 4096
    hist_rows_kernel<<<rows, THREADS>>>(x, out);
}